// round 15
// baseline (speedup 1.0000x reference)
#include <cuda_runtime.h>
#include <cuda_bf16.h>
#include <cstdint>

// Problem constants: B=16, N1=1024, N2=4096, DIM=512
// GEMM1: M=16384, K=1024, N=512.  GEMM2: M=65536, K=512, N=512.

// ---------------- scratch (no allocations allowed) -------------------------
__device__ float g_h1[16384 * 512];
__device__ float g_h2[65536 * 512];
__device__ float g_part[2 * 512 * 512];    // sums | sumsq (rows 0-255 g2, 256-319 g1)
__device__ float g_ss[4 * 512];            // scale1, shift1, scale2, shift2
__device__ float4 g_kw[65536];             // 3-NN weights per dst point
__device__ int4 g_ki[65536];               // 3-NN global feats1 row ids
__device__ __nv_bfloat16 g_w1h[512 * 1024];
__device__ __nv_bfloat16 g_w1l[512 * 1024];
__device__ __nv_bfloat16 g_w2h[512 * 512];
__device__ __nv_bfloat16 g_w2l[512 * 512];

// ---------------- low-level helpers ----------------------------------------
__device__ __forceinline__ uint32_t smem_to_u32(const void* p) {
  uint32_t a;
  asm("{ .reg .u64 t; cvta.to.shared.u64 t, %1; cvt.u32.u64 %0, t; }"
      : "=r"(a) : "l"(p));
  return a;
}
__device__ __forceinline__ void cp_async16(uint32_t dst, const void* src) {
  asm volatile("cp.async.cg.shared.global [%0], [%1], 16;" ::"r"(dst),
               "l"(src));
}
#define CP_COMMIT() asm volatile("cp.async.commit_group;" ::: "memory")
#define CP_WAIT(N) asm volatile("cp.async.wait_group %0;" ::"n"(N) : "memory")

__device__ __forceinline__ void ldsm_x4(uint32_t (&r)[4], uint32_t addr) {
  asm volatile(
      "ldmatrix.sync.aligned.m8n8.x4.shared.b16 {%0,%1,%2,%3}, [%4];"
      : "=r"(r[0]), "=r"(r[1]), "=r"(r[2]), "=r"(r[3])
      : "r"(addr));
}
__device__ __forceinline__ void lds64(float& f0, float& f1, uint32_t addr) {
  asm volatile("ld.shared.v2.f32 {%0,%1}, [%2];"
               : "=f"(f0), "=f"(f1) : "r"(addr));
}
// fp32 pair -> hi bf16x2 (truncation) + lo bf16x2 (residual, RN)
__device__ __forceinline__ void split_pair(float f0, float f1, uint32_t& h,
                                           uint32_t& l) {
  uint32_t u0 = __float_as_uint(f0), u1 = __float_as_uint(f1);
  h = __byte_perm(u0, u1, 0x7632);  // [u1.hi16 | u0.hi16]
  float r0 = f0 - __uint_as_float(u0 & 0xffff0000u);
  float r1 = f1 - __uint_as_float(u1 & 0xffff0000u);
  asm("cvt.rn.bf16x2.f32 %0, %1, %2;" : "=r"(l) : "f"(r1), "f"(r0));
}
__device__ __forceinline__ void mma_bf16(float (&c)[4], const uint32_t (&a)[4],
                                         uint32_t b0, uint32_t b1) {
  asm("mma.sync.aligned.m16n8k16.row.col.f32.bf16.bf16.f32 "
      "{%0,%1,%2,%3}, {%4,%5,%6,%7}, {%8,%9}, {%0,%1,%2,%3};"
      : "+f"(c[0]), "+f"(c[1]), "+f"(c[2]), "+f"(c[3])
      : "r"(a[0]), "r"(a[1]), "r"(a[2]), "r"(a[3]), "r"(b0), "r"(b1));
}

// ---------------------------------------------------------------------------
// Both weights in one launch: W [K,512] -> Wt hi/lo [512,K] transpose + split.
// ---------------------------------------------------------------------------
__global__ void __launch_bounds__(256) wsplit_all(
    const float* __restrict__ W1, __nv_bfloat16* __restrict__ T1h,
    __nv_bfloat16* __restrict__ T1l, const float* __restrict__ W2,
    __nv_bfloat16* __restrict__ T2h, __nv_bfloat16* __restrict__ T2l) {
  __shared__ float tl[32][33];
  const bool first = blockIdx.x < 32;
  const int K = first ? 1024 : 512;
  const float* W = first ? W1 : W2;
  __nv_bfloat16* Th = first ? T1h : T2h;
  __nv_bfloat16* Tl = first ? T1l : T2l;
  int k0 = (first ? blockIdx.x : (blockIdx.x - 32)) * 32;
  int n0 = blockIdx.y * 32;
  int x = threadIdx.x & 31, y = threadIdx.x >> 5;  // 32x8
  for (int i = y; i < 32; i += 8)
    tl[i][x] = W[(size_t)(k0 + i) * 512 + n0 + x];
  __syncthreads();
  for (int i = y; i < 32; i += 8) {
    float v = tl[x][i];  // = W[k0+x][n0+i]
    __nv_bfloat16 h = __float2bfloat16(v);
    __nv_bfloat16 l = __float2bfloat16(v - __bfloat162float(h));
    Th[(size_t)(n0 + i) * K + k0 + x] = h;
    Tl[(size_t)(n0 + i) * K + k0 + x] = l;
  }
}

// ---------------------------------------------------------------------------
// bf16x3 GEMM via mma.sync, BOTH GEMMs in ONE launch. LPT dispatch: the LONG
// fc1 CTAs (K=1024) are blocks 0..255 (scheduled FIRST), short fc2 CTAs
// (K=512) are blocks 256..1279 — the trailing partial wave is then composed
// of short blocks, cutting the makespan tail. CTA tile 256x128, Kc=32,
// three-buffer single-barrier pipeline, 512 thr, warp grid 4m x 4n.
// Epilogue emits per-CTA BN partials.
// ---------------------------------------------------------------------------
static constexpr int A_RS = 160;                  // 32 fp32 + 32B pad (bank-clean)
static constexpr int A_BYTES = 256 * A_RS;        // 40960 B
static constexpr int B_RS = 80;                   // 32 bf16 + 16B pad
static constexpr int B_TILE = 128 * B_RS;         // 10240 B
static constexpr int G_STAGE = A_BYTES + 2 * B_TILE;  // 61440 B
static constexpr int GEMM_SMEM = 3 * G_STAGE;     // 184320 B

__device__ __forceinline__ void stage_load(
    const float* __restrict__ A, const __nv_bfloat16* __restrict__ Bh,
    const __nv_bfloat16* __restrict__ Bl, int K, int bm, int bn, int k0,
    uint32_t base, int tid) {
  // A fp32 tile: 256 rows x 8 ld16 (128B) = 2048 -> 4 per thread
  {
    const float* sa = A + (size_t)bm * K;
#pragma unroll
    for (int i = 0; i < 4; i++) {
      int q = tid + i * 512;  // 0..2047
      int row = q >> 3, seg = q & 7;
      cp_async16(base + row * A_RS + seg * 16,
                 sa + (size_t)row * K + k0 + seg * 4);
    }
  }
  // B hi/lo bf16 tiles: 128 rows x 4 ld16 (64B) = 512 each -> 1 per thread
  {
    const __nv_bfloat16* sbh = Bh + (size_t)bn * K;
    const __nv_bfloat16* sbl = Bl + (size_t)bn * K;
    int row = tid >> 2, seg = tid & 3;
    size_t go = (size_t)row * K + k0 + seg * 8;
    uint32_t so = row * B_RS + seg * 16;
    cp_async16(base + A_BYTES + so, sbh + go);
    cp_async16(base + A_BYTES + B_TILE + so, sbl + go);
  }
}

__device__ __forceinline__ void stage_compute(uint32_t base, int warp_m,
                                              int warp_n, int lid,
                                              float acc[4][4][4]) {
  const uint32_t aF = base + (warp_m * 64 + (lid >> 2)) * A_RS + (lid & 3) * 8;
  const int nrow = warp_n * 32 + (lid & 7) + ((lid >> 4) & 1) * 8;
  const uint32_t b_base =
      base + A_BYTES + nrow * B_RS + ((lid >> 3) & 1) * 16;
#pragma unroll
  for (int kk = 0; kk < 2; kk++) {
    uint32_t ah[4][4], al[4][4], bh[2][4], bl[2][4];
    const uint32_t akk = aF + kk * 64;
#pragma unroll
    for (int i = 0; i < 4; i++) {
      const uint32_t ai = akk + i * (16 * A_RS);
#pragma unroll
      for (int r = 0; r < 4; r++) {
        float f0, f1;
        lds64(f0, f1, ai + (r & 1) * (8 * A_RS) + (r >> 1) * 32);
        split_pair(f0, f1, ah[i][r], al[i][r]);
      }
    }
    const int kb = kk * 32;
#pragma unroll
    for (int jj = 0; jj < 2; jj++) {
      ldsm_x4(bh[jj], b_base + jj * (16 * B_RS) + kb);
      ldsm_x4(bl[jj], b_base + B_TILE + jj * (16 * B_RS) + kb);
    }
#pragma unroll
    for (int i = 0; i < 4; i++)
#pragma unroll
      for (int j = 0; j < 4; j++) {
        const int jj = j >> 1, o = (j & 1) * 2;
        mma_bf16(acc[i][j], ah[i], bh[jj][o], bh[jj][o + 1]);
      }
#pragma unroll
    for (int i = 0; i < 4; i++)
#pragma unroll
      for (int j = 0; j < 4; j++) {
        const int jj = j >> 1, o = (j & 1) * 2;
        mma_bf16(acc[i][j], ah[i], bl[jj][o], bl[jj][o + 1]);
      }
#pragma unroll
    for (int i = 0; i < 4; i++)
#pragma unroll
      for (int j = 0; j < 4; j++) {
        const int jj = j >> 1, o = (j & 1) * 2;
        mma_bf16(acc[i][j], al[i], bh[jj][o], bh[jj][o + 1]);
      }
  }
}

__global__ void __launch_bounds__(512, 1) gemm_all(
    const float* __restrict__ A1, const __nv_bfloat16* __restrict__ B1h,
    const __nv_bfloat16* __restrict__ B1l, const float* __restrict__ bias1,
    float* __restrict__ C1, const float* __restrict__ A2,
    const __nv_bfloat16* __restrict__ B2h,
    const __nv_bfloat16* __restrict__ B2l, const float* __restrict__ bias2,
    float* __restrict__ C2, float* __restrict__ part) {
  extern __shared__ char smem[];
  const uint32_t sb = smem_to_u32(smem);
  const int tid = threadIdx.x;
  const int wid = tid >> 5, lid = tid & 31;
  const int warp_m = wid & 3, warp_n = wid >> 2;

  // LPT dispatch: blocks 0..255 -> fc1 (K=1024, LONG, first);
  //               blocks 256..1279 -> fc2 (K=512, short, tail)
  const float* A;
  const __nv_bfloat16 *Bh, *Bl;
  const float* bias;
  float* C;
  int K, bm, bn, prow;
  if (blockIdx.x < 256) {
    int t = blockIdx.x;
    A = A1; Bh = B1h; Bl = B1l; bias = bias1; C = C1;
    K = 1024; bn = (t & 3) * 128; bm = (t >> 2) * 256; prow = 256 + (t >> 2);
  } else {
    int t = blockIdx.x - 256;
    A = A2; Bh = B2h; Bl = B2l; bias = bias2; C = C2;
    K = 512; bn = (t & 3) * 128; bm = (t >> 2) * 256; prow = t >> 2;
  }
  const int NS = K / 32;

  float acc[4][4][4];
#pragma unroll
  for (int i = 0; i < 4; i++)
#pragma unroll
    for (int j = 0; j < 4; j++)
#pragma unroll
      for (int r = 0; r < 4; r++) acc[i][j][r] = 0.0f;

  // prologue: stages 0,1 into bufs 0,1
  stage_load(A, Bh, Bl, K, bm, bn, 0, sb, tid);
  CP_COMMIT();
  stage_load(A, Bh, Bl, K, bm, bn, 32, sb + G_STAGE, tid);
  CP_COMMIT();

  int b0 = 0, b1 = G_STAGE, b2 = 2 * G_STAGE;  // bufs for s, s+1, s+2 (mod 3)
  for (int s = 0; s < NS; s++) {
    CP_WAIT(1);          // group s complete (group s+1 may be pending)
    __syncthreads();     // data of stage s visible; buf of stage s-1 free
    if (s + 2 < NS)      // issue load s+2 into the freed buffer
      stage_load(A, Bh, Bl, K, bm, bn, (s + 2) * 32, sb + b2, tid);
    CP_COMMIT();         // always commit (empty group at tail keeps counts)
    stage_compute(sb + b0, warp_m, warp_n, lid, acc);
    int t = b0; b0 = b1; b1 = b2; b2 = t;  // rotate
  }
  __syncthreads();  // all compute done before smem reuse below

  // ---- epilogue: +bias, store C, per-CTA column sum/sumsq partials ----
  const int g = lid >> 2, tq = lid & 3;
  float s8[4][2], q8[4][2];
#pragma unroll
  for (int j = 0; j < 4; j++) {
    const int n = bn + warp_n * 32 + j * 8 + tq * 2;
    const float2 bv = *reinterpret_cast<const float2*>(bias + n);
    float sv[2] = {0.0f, 0.0f}, qv[2] = {0.0f, 0.0f};
#pragma unroll
    for (int i = 0; i < 4; i++) {
      const int m = bm + warp_m * 64 + i * 16 + g;
      acc[i][j][0] += bv.x;
      acc[i][j][1] += bv.y;
      acc[i][j][2] += bv.x;
      acc[i][j][3] += bv.y;
      float2 r0 = {acc[i][j][0], acc[i][j][1]};
      float2 r1 = {acc[i][j][2], acc[i][j][3]};
      *reinterpret_cast<float2*>(C + (size_t)m * 512 + n) = r0;
      *reinterpret_cast<float2*>(C + (size_t)(m + 8) * 512 + n) = r1;
#pragma unroll
      for (int p = 0; p < 2; p++) {
        sv[p] += acc[i][j][p] + acc[i][j][p + 2];
        qv[p] += acc[i][j][p] * acc[i][j][p] +
                 acc[i][j][p + 2] * acc[i][j][p + 2];
      }
    }
#pragma unroll
    for (int p = 0; p < 2; p++) {
      float svv = sv[p], qvv = qv[p];
      svv += __shfl_down_sync(0xffffffffu, svv, 16);
      qvv += __shfl_down_sync(0xffffffffu, qvv, 16);
      svv += __shfl_down_sync(0xffffffffu, svv, 8);
      qvv += __shfl_down_sync(0xffffffffu, qvv, 8);
      svv += __shfl_down_sync(0xffffffffu, svv, 4);
      qvv += __shfl_down_sync(0xffffffffu, qvv, 4);
      s8[j][p] = svv;
      q8[j][p] = qvv;
    }
  }
  __syncthreads();
  float* red = reinterpret_cast<float*>(smem);
  if (lid < 4) {
#pragma unroll
    for (int j = 0; j < 4; j++)
#pragma unroll
      for (int p = 0; p < 2; p++) {
        int c = warp_n * 32 + j * 8 + lid * 2 + p;  // lid == tq here
        red[warp_m * 128 + c] = s8[j][p];
        red[512 + warp_m * 128 + c] = q8[j][p];
      }
  }
  __syncthreads();
  if (tid < 128) {
    float s = red[tid] + red[128 + tid] + red[256 + tid] + red[384 + tid];
    float q = red[512 + tid] + red[640 + tid] + red[768 + tid] + red[896 + tid];
    part[(size_t)prow * 512 + bn + tid] = s;
    part[262144 + (size_t)prow * 512 + bn + tid] = q;
  }
}

// ---------------------------------------------------------------------------
// BN stats finalize: ONE launch, one block per (path, channel). grid=1024:
// blocks 0..511 -> path2 (rows 0..255), 512..1023 -> path1 (rows 256..319).
// ---------------------------------------------------------------------------
__global__ void __launch_bounds__(256) stats_finalize_all(
    const float* __restrict__ part, const float* __restrict__ bn1_g,
    const float* __restrict__ bn1_b, const float* __restrict__ bn2_g,
    const float* __restrict__ bn2_b, float* __restrict__ ss) {
  __shared__ float rs[256], rq[256];
  const int t = threadIdx.x;
  const bool path1 = blockIdx.x >= 512;
  const int c = blockIdx.x & 511;
  const int row0 = path1 ? 256 : 0;
  const int NBLK = path1 ? 64 : 256;
  const float invM = path1 ? (1.0f / 16384.0f) : (1.0f / 65536.0f);

  float s = 0.0f, q = 0.0f;
  if (t < NBLK) {
    s = part[(size_t)(row0 + t) * 512 + c];
    q = part[262144 + (size_t)(row0 + t) * 512 + c];
  }
  rs[t] = s;
  rq[t] = q;
  __syncthreads();
#pragma unroll
  for (int off = 128; off > 0; off >>= 1) {
    if (t < off) {
      rs[t] += rs[t + off];
      rq[t] += rq[t + off];
    }
    __syncthreads();
  }
  if (t == 0) {
    float mu = rs[0] * invM;
    float var = rq[0] * invM - mu * mu;
    const float* gamma = path1 ? bn1_g : bn2_g;
    const float* beta = path1 ? bn1_b : bn2_b;
    float* dst = path1 ? ss : (ss + 1024);
    float sc = gamma[c] * rsqrtf(var + 1e-5f);
    dst[c] = sc;
    dst[512 + c] = beta[c] - mu * sc;
  }
}

// ---------------------------------------------------------------------------
// 3-NN search only: warp-synchronous, register-resident distances.
// ---------------------------------------------------------------------------
__global__ void __launch_bounds__(256) knn(
    const float* __restrict__ xyz2, const float* __restrict__ xyz1,
    float4* __restrict__ kw, int4* __restrict__ ki) {
  __shared__ float sx[1024], sy[1024], sz[1024];  // xyz1 SoA (12 KB)

  const int tid = threadIdx.x;
  const int w = tid >> 5, lane = tid & 31;
  const int b = blockIdx.x >> 9;
  const int nb = (blockIdx.x & 511) * 8;

  const float* src = xyz1 + (size_t)b * 3072;
  for (int i = tid; i < 1024; i += 256) {
    sx[i] = src[3 * i + 0];
    sy[i] = src[3 * i + 1];
    sz[i] = src[3 * i + 2];
  }
  __syncthreads();

  const int n = nb + w;
  const int p = b * 4096 + n;
  const float* pd = xyz2 + (size_t)p * 3;
  const float px = pd[0], py = pd[1], pz = pd[2];
  const float pp = px * px + py * py + pz * pz;

  float d[32];
#pragma unroll
  for (int j = 0; j < 32; j++) {
    int s = lane + j * 32;
    float xx = sx[s], yy = sy[s], zz = sz[s];
    d[j] = pp + (xx * xx + yy * yy + zz * zz) -
           2.0f * (px * xx + py * yy + pz * zz);
  }

  float bv[3];
  int bi3[3];
#pragma unroll
  for (int round = 0; round < 3; round++) {
    float m = d[0];
#pragma unroll
    for (int j = 1; j < 32; j++) m = fminf(m, d[j]);
#pragma unroll
    for (int off = 16; off; off >>= 1)
      m = fminf(m, __shfl_xor_sync(0xffffffffu, m, off));
    int li = 0x7fffffff;
#pragma unroll
    for (int j = 0; j < 32; j++)
      if (d[j] == m) li = min(li, lane + j * 32);
#pragma unroll
    for (int off = 16; off; off >>= 1)
      li = min(li, __shfl_xor_sync(0xffffffffu, li, off));
    bv[round] = m;
    bi3[round] = li;
    if ((li & 31) == lane) {
      const int slot = li >> 5;
#pragma unroll
      for (int j = 0; j < 32; j++)
        if (j == slot) d[j] = 1e30f;
    }
  }

  if (lane == 0) {
    float w0 = 1.0f / (bv[0] + 1e-8f);
    float w1 = 1.0f / (bv[1] + 1e-8f);
    float w2 = 1.0f / (bv[2] + 1e-8f);
    float inv = 1.0f / (w0 + w1 + w2);
    kw[p] = float4{w0 * inv, w1 * inv, w2 * inv, 0.0f};
    ki[p] = int4{b * 1024 + bi3[0], b * 1024 + bi3[1], b * 1024 + bi3[2], 0};
  }
}

// ---------------------------------------------------------------------------
// Apply: gather 3 feats1 rows + feats2 row, fused BN+ReLU, weighted add.
// ---------------------------------------------------------------------------
__global__ void __launch_bounds__(256) apply_add(
    const float* __restrict__ feats1, const float* __restrict__ feats2,
    const float4* __restrict__ kw, const int4* __restrict__ ki,
    const float* __restrict__ ss1, const float* __restrict__ ss2,
    float* __restrict__ outF) {
  const int lane = threadIdx.x & 31;
  const int row = blockIdx.x * 8 + (threadIdx.x >> 5);

  const float4 wv = kw[row];
  const int4 id = ki[row];
  const float w0 = wv.x, w1 = wv.y, w2 = wv.z;

  const float4* f0 = reinterpret_cast<const float4*>(feats1 + (size_t)id.x * 512);
  const float4* f1 = reinterpret_cast<const float4*>(feats1 + (size_t)id.y * 512);
  const float4* f2 = reinterpret_cast<const float4*>(feats1 + (size_t)id.z * 512);
  const float4* g = reinterpret_cast<const float4*>(feats2 + (size_t)row * 512);
  float4* o = reinterpret_cast<float4*>(outF + (size_t)row * 512);
  const float4* SC1 = reinterpret_cast<const float4*>(ss1);
  const float4* SH1 = reinterpret_cast<const float4*>(ss1 + 512);
  const float4* SC2 = reinterpret_cast<const float4*>(ss2);
  const float4* SH2 = reinterpret_cast<const float4*>(ss2 + 512);

#pragma unroll
  for (int c4 = lane; c4 < 128; c4 += 32) {
    float4 a0 = f0[c4], a1 = f1[c4], a2 = f2[c4], gg = g[c4];
    float4 sc1 = SC1[c4], sh1 = SH1[c4], sc2 = SC2[c4], sh2 = SH2[c4];
    a0.x = fmaxf(fmaf(a0.x, sc1.x, sh1.x), 0.0f);
    a0.y = fmaxf(fmaf(a0.y, sc1.y, sh1.y), 0.0f);
    a0.z = fmaxf(fmaf(a0.z, sc1.z, sh1.z), 0.0f);
    a0.w = fmaxf(fmaf(a0.w, sc1.w, sh1.w), 0.0f);
    a1.x = fmaxf(fmaf(a1.x, sc1.x, sh1.x), 0.0f);
    a1.y = fmaxf(fmaf(a1.y, sc1.y, sh1.y), 0.0f);
    a1.z = fmaxf(fmaf(a1.z, sc1.z, sh1.z), 0.0f);
    a1.w = fmaxf(fmaf(a1.w, sc1.w, sh1.w), 0.0f);
    a2.x = fmaxf(fmaf(a2.x, sc1.x, sh1.x), 0.0f);
    a2.y = fmaxf(fmaf(a2.y, sc1.y, sh1.y), 0.0f);
    a2.z = fmaxf(fmaf(a2.z, sc1.z, sh1.z), 0.0f);
    a2.w = fmaxf(fmaf(a2.w, sc1.w, sh1.w), 0.0f);
    gg.x = fmaxf(fmaf(gg.x, sc2.x, sh2.x), 0.0f);
    gg.y = fmaxf(fmaf(gg.y, sc2.y, sh2.y), 0.0f);
    gg.z = fmaxf(fmaf(gg.z, sc2.z, sh2.z), 0.0f);
    gg.w = fmaxf(fmaf(gg.w, sc2.w, sh2.w), 0.0f);
    float4 r;
    r.x = w0 * a0.x + w1 * a1.x + w2 * a2.x + gg.x;
    r.y = w0 * a0.y + w1 * a1.y + w2 * a2.y + gg.y;
    r.z = w0 * a0.z + w1 * a1.z + w2 * a2.z + gg.z;
    r.w = w0 * a0.w + w1 * a1.w + w2 * a2.w + gg.w;
    o[c4] = r;
  }
}

// ---------------------------------------------------------------------------
extern "C" void kernel_launch(void* const* d_in, const int* in_sizes, int n_in,
                              void* d_out, int out_size) {
  const float* xyz1 = (const float*)d_in[0];
  const float* points1 = (const float*)d_in[1];
  const float* xyz2 = (const float*)d_in[2];
  const float* points2 = (const float*)d_in[3];
  const float* fc1_w = (const float*)d_in[4];
  const float* fc1_b = (const float*)d_in[5];
  const float* bn1_g = (const float*)d_in[6];
  const float* bn1_b = (const float*)d_in[7];
  const float* fc2_w = (const float*)d_in[8];
  const float* fc2_b = (const float*)d_in[9];
  const float* bn2_g = (const float*)d_in[10];
  const float* bn2_b = (const float*)d_in[11];
  float* out = (float*)d_out;

  float *h1, *h2, *part, *ss;
  float4* kw;
  int4* ki;
  __nv_bfloat16 *w1h, *w1l, *w2h, *w2l;
  cudaGetSymbolAddress((void**)&h1, g_h1);
  cudaGetSymbolAddress((void**)&h2, g_h2);
  cudaGetSymbolAddress((void**)&part, g_part);
  cudaGetSymbolAddress((void**)&ss, g_ss);
  cudaGetSymbolAddress((void**)&kw, g_kw);
  cudaGetSymbolAddress((void**)&ki, g_ki);
  cudaGetSymbolAddress((void**)&w1h, g_w1h);
  cudaGetSymbolAddress((void**)&w1l, g_w1l);
  cudaGetSymbolAddress((void**)&w2h, g_w2h);
  cudaGetSymbolAddress((void**)&w2l, g_w2l);

  cudaFuncSetAttribute(gemm_all, cudaFuncAttributeMaxDynamicSharedMemorySize,
                       GEMM_SMEM);

  const size_t featElems = (size_t)16 * 4096 * 512;
  const size_t totalOut = (size_t)out_size;
  const size_t xyzElems = totalOut > featElems ? totalOut - featElems : 0;

  // launch 1: weight transpose + split
  wsplit_all<<<dim3(48, 16), 256>>>(fc1_w, w1h, w1l, fc2_w, w2h, w2l);

  // launch 2: 3-NN search (independent of GEMMs)
  knn<<<8192, 256>>>(xyz2, xyz1, kw, ki);

  // launch 3: BOTH GEMMs, long fc1 blocks first (LPT tail shortening)
  gemm_all<<<1280, 512, GEMM_SMEM>>>(points1, w1h, w1l, fc1_b, h1, points2,
                                     w2h, w2l, fc2_b, h2, part);

  // launch 4: BN stats for both paths
  stats_finalize_all<<<1024, 256>>>(part, bn1_g, bn1_b, bn2_g, bn2_b, ss);

  // Output: [xyz2 passthrough | apply(bnrelu(h1) gather) + bnrelu(h2)]
  if (xyzElems > 0) {
    cudaMemcpyAsync(out, xyz2, xyzElems * sizeof(float),
                    cudaMemcpyDeviceToDevice);
  }
  // launch 5: streaming gather+BN+add (high occupancy)
  apply_add<<<8192, 256>>>(h1, h2, kw, ki, ss, ss + 1024, out + xyzElems);
}

// round 16
// speedup vs baseline: 1.0318x; 1.0318x over previous
#include <cuda_runtime.h>
#include <cuda_bf16.h>
#include <cstdint>

// Problem constants: B=16, N1=1024, N2=4096, DIM=512
// GEMM1: M=16384, K=1024, N=512.  GEMM2: M=65536, K=512, N=512.

// ---------------- scratch (no allocations allowed) -------------------------
__device__ float g_h1[16384 * 512];
__device__ float g_h2[65536 * 512];
__device__ float g_part[2 * 512 * 512];    // sums | sumsq (rows 0-255 g2, 256-319 g1)
__device__ float g_ss[4 * 512];            // scale1, shift1, scale2, shift2
__device__ float4 g_kw[65536];             // 3-NN weights per dst point
__device__ int4 g_ki[65536];               // 3-NN global feats1 row ids
__device__ __nv_bfloat16 g_w1h[512 * 1024];
__device__ __nv_bfloat16 g_w1l[512 * 1024];
__device__ __nv_bfloat16 g_w2h[512 * 512];
__device__ __nv_bfloat16 g_w2l[512 * 512];

// ---------------- low-level helpers ----------------------------------------
__device__ __forceinline__ uint32_t smem_to_u32(const void* p) {
  uint32_t a;
  asm("{ .reg .u64 t; cvta.to.shared.u64 t, %1; cvt.u32.u64 %0, t; }"
      : "=r"(a) : "l"(p));
  return a;
}
__device__ __forceinline__ void cp_async16(uint32_t dst, const void* src) {
  asm volatile("cp.async.cg.shared.global [%0], [%1], 16;" ::"r"(dst),
               "l"(src));
}
#define CP_COMMIT() asm volatile("cp.async.commit_group;" ::: "memory")
#define CP_WAIT(N) asm volatile("cp.async.wait_group %0;" ::"n"(N) : "memory")

__device__ __forceinline__ void ldsm_x4(uint32_t (&r)[4], uint32_t addr) {
  asm volatile(
      "ldmatrix.sync.aligned.m8n8.x4.shared.b16 {%0,%1,%2,%3}, [%4];"
      : "=r"(r[0]), "=r"(r[1]), "=r"(r[2]), "=r"(r[3])
      : "r"(addr));
}
__device__ __forceinline__ void lds64(float& f0, float& f1, uint32_t addr) {
  asm volatile("ld.shared.v2.f32 {%0,%1}, [%2];"
               : "=f"(f0), "=f"(f1) : "r"(addr));
}
// fp32 pair -> hi bf16x2 (truncation) + lo bf16x2 (residual, RN)
__device__ __forceinline__ void split_pair(float f0, float f1, uint32_t& h,
                                           uint32_t& l) {
  uint32_t u0 = __float_as_uint(f0), u1 = __float_as_uint(f1);
  h = __byte_perm(u0, u1, 0x7632);  // [u1.hi16 | u0.hi16]
  float r0 = f0 - __uint_as_float(u0 & 0xffff0000u);
  float r1 = f1 - __uint_as_float(u1 & 0xffff0000u);
  asm("cvt.rn.bf16x2.f32 %0, %1, %2;" : "=r"(l) : "f"(r1), "f"(r0));
}
__device__ __forceinline__ void mma_bf16(float (&c)[4], const uint32_t (&a)[4],
                                         uint32_t b0, uint32_t b1) {
  asm("mma.sync.aligned.m16n8k16.row.col.f32.bf16.bf16.f32 "
      "{%0,%1,%2,%3}, {%4,%5,%6,%7}, {%8,%9}, {%0,%1,%2,%3};"
      : "+f"(c[0]), "+f"(c[1]), "+f"(c[2]), "+f"(c[3])
      : "r"(a[0]), "r"(a[1]), "r"(a[2]), "r"(a[3]), "r"(b0), "r"(b1));
}

// ---------------------------------------------------------------------------
// Both weights in one launch: W [K,512] -> Wt hi/lo [512,K] transpose + split.
// ---------------------------------------------------------------------------
__global__ void __launch_bounds__(256) wsplit_all(
    const float* __restrict__ W1, __nv_bfloat16* __restrict__ T1h,
    __nv_bfloat16* __restrict__ T1l, const float* __restrict__ W2,
    __nv_bfloat16* __restrict__ T2h, __nv_bfloat16* __restrict__ T2l) {
  __shared__ float tl[32][33];
  const bool first = blockIdx.x < 32;
  const int K = first ? 1024 : 512;
  const float* W = first ? W1 : W2;
  __nv_bfloat16* Th = first ? T1h : T2h;
  __nv_bfloat16* Tl = first ? T1l : T2l;
  int k0 = (first ? blockIdx.x : (blockIdx.x - 32)) * 32;
  int n0 = blockIdx.y * 32;
  int x = threadIdx.x & 31, y = threadIdx.x >> 5;  // 32x8
  for (int i = y; i < 32; i += 8)
    tl[i][x] = W[(size_t)(k0 + i) * 512 + n0 + x];
  __syncthreads();
  for (int i = y; i < 32; i += 8) {
    float v = tl[x][i];  // = W[k0+x][n0+i]
    __nv_bfloat16 h = __float2bfloat16(v);
    __nv_bfloat16 l = __float2bfloat16(v - __bfloat162float(h));
    Th[(size_t)(n0 + i) * K + k0 + x] = h;
    Tl[(size_t)(n0 + i) * K + k0 + x] = l;
  }
}

// ---------------------------------------------------------------------------
// FUSED launch: blocks 0..255 -> fc1 GEMM (K=1024); 256..1279 -> fc2 GEMM
// (K=512); 1280..5375 -> 3-NN knn blocks (16 points each) that BACKFILL the
// GEMM's ragged tail waves. bf16x3 GEMM via mma.sync: CTA tile 256x128,
// Kc=32, three-buffer single-barrier pipeline, 512 thr, warp grid 4m x 4n.
// Epilogue emits per-CTA BN partials.
// ---------------------------------------------------------------------------
static constexpr int A_RS = 160;                  // 32 fp32 + 32B pad (bank-clean)
static constexpr int A_BYTES = 256 * A_RS;        // 40960 B
static constexpr int B_RS = 80;                   // 32 bf16 + 16B pad
static constexpr int B_TILE = 128 * B_RS;         // 10240 B
static constexpr int G_STAGE = A_BYTES + 2 * B_TILE;  // 61440 B
static constexpr int GEMM_SMEM = 3 * G_STAGE;     // 184320 B

__device__ __forceinline__ void stage_load(
    const float* __restrict__ A, const __nv_bfloat16* __restrict__ Bh,
    const __nv_bfloat16* __restrict__ Bl, int K, int bm, int bn, int k0,
    uint32_t base, int tid) {
  // A fp32 tile: 256 rows x 8 ld16 (128B) = 2048 -> 4 per thread
  {
    const float* sa = A + (size_t)bm * K;
#pragma unroll
    for (int i = 0; i < 4; i++) {
      int q = tid + i * 512;  // 0..2047
      int row = q >> 3, seg = q & 7;
      cp_async16(base + row * A_RS + seg * 16,
                 sa + (size_t)row * K + k0 + seg * 4);
    }
  }
  // B hi/lo bf16 tiles: 128 rows x 4 ld16 (64B) = 512 each -> 1 per thread
  {
    const __nv_bfloat16* sbh = Bh + (size_t)bn * K;
    const __nv_bfloat16* sbl = Bl + (size_t)bn * K;
    int row = tid >> 2, seg = tid & 3;
    size_t go = (size_t)row * K + k0 + seg * 8;
    uint32_t so = row * B_RS + seg * 16;
    cp_async16(base + A_BYTES + so, sbh + go);
    cp_async16(base + A_BYTES + B_TILE + so, sbl + go);
  }
}

__device__ __forceinline__ void stage_compute(uint32_t base, int warp_m,
                                              int warp_n, int lid,
                                              float acc[4][4][4]) {
  const uint32_t aF = base + (warp_m * 64 + (lid >> 2)) * A_RS + (lid & 3) * 8;
  const int nrow = warp_n * 32 + (lid & 7) + ((lid >> 4) & 1) * 8;
  const uint32_t b_base =
      base + A_BYTES + nrow * B_RS + ((lid >> 3) & 1) * 16;
#pragma unroll
  for (int kk = 0; kk < 2; kk++) {
    uint32_t ah[4][4], al[4][4], bh[2][4], bl[2][4];
    const uint32_t akk = aF + kk * 64;
#pragma unroll
    for (int i = 0; i < 4; i++) {
      const uint32_t ai = akk + i * (16 * A_RS);
#pragma unroll
      for (int r = 0; r < 4; r++) {
        float f0, f1;
        lds64(f0, f1, ai + (r & 1) * (8 * A_RS) + (r >> 1) * 32);
        split_pair(f0, f1, ah[i][r], al[i][r]);
      }
    }
    const int kb = kk * 32;
#pragma unroll
    for (int jj = 0; jj < 2; jj++) {
      ldsm_x4(bh[jj], b_base + jj * (16 * B_RS) + kb);
      ldsm_x4(bl[jj], b_base + B_TILE + jj * (16 * B_RS) + kb);
    }
#pragma unroll
    for (int i = 0; i < 4; i++)
#pragma unroll
      for (int j = 0; j < 4; j++) {
        const int jj = j >> 1, o = (j & 1) * 2;
        mma_bf16(acc[i][j], ah[i], bh[jj][o], bh[jj][o + 1]);
      }
#pragma unroll
    for (int i = 0; i < 4; i++)
#pragma unroll
      for (int j = 0; j < 4; j++) {
        const int jj = j >> 1, o = (j & 1) * 2;
        mma_bf16(acc[i][j], ah[i], bl[jj][o], bl[jj][o + 1]);
      }
#pragma unroll
    for (int i = 0; i < 4; i++)
#pragma unroll
      for (int j = 0; j < 4; j++) {
        const int jj = j >> 1, o = (j & 1) * 2;
        mma_bf16(acc[i][j], al[i], bh[jj][o], bh[jj][o + 1]);
      }
  }
}

__global__ void __launch_bounds__(512, 1) gemm_knn_all(
    const float* __restrict__ A1, const __nv_bfloat16* __restrict__ B1h,
    const __nv_bfloat16* __restrict__ B1l, const float* __restrict__ bias1,
    float* __restrict__ C1, const float* __restrict__ A2,
    const __nv_bfloat16* __restrict__ B2h,
    const __nv_bfloat16* __restrict__ B2l, const float* __restrict__ bias2,
    float* __restrict__ C2, float* __restrict__ part,
    const float* __restrict__ xyz2, const float* __restrict__ xyz1,
    float4* __restrict__ kw, int4* __restrict__ ki) {
  extern __shared__ char smem[];
  const uint32_t sb = smem_to_u32(smem);
  const int tid = threadIdx.x;
  const int wid = tid >> 5, lid = tid & 31;

  // ======================= knn blocks (tail backfill) ======================
  if (blockIdx.x >= 1280) {
    float* sx = reinterpret_cast<float*>(smem);
    float* sy = sx + 1024;
    float* sz = sy + 1024;
    const int kb = blockIdx.x - 1280;     // 0..4095
    const int b = kb >> 8;                // 256 blocks per batch
    const int nb = (kb & 255) * 16;       // 16 points per block
    const int w = wid, lane = lid;

    const float* src = xyz1 + (size_t)b * 3072;
    for (int i = tid; i < 1024; i += 512) {
      sx[i] = src[3 * i + 0];
      sy[i] = src[3 * i + 1];
      sz[i] = src[3 * i + 2];
    }
    __syncthreads();

    const int n = nb + w;
    const int p = b * 4096 + n;
    const float* pd = xyz2 + (size_t)p * 3;
    const float px = pd[0], py = pd[1], pz = pd[2];
    const float pp = px * px + py * py + pz * pz;

    float d[32];
#pragma unroll
    for (int j = 0; j < 32; j++) {
      int s = lane + j * 32;
      float xx = sx[s], yy = sy[s], zz = sz[s];
      d[j] = pp + (xx * xx + yy * yy + zz * zz) -
             2.0f * (px * xx + py * yy + pz * zz);
    }

    float bv[3];
    int bi3[3];
#pragma unroll
    for (int round = 0; round < 3; round++) {
      float m = d[0];
#pragma unroll
      for (int j = 1; j < 32; j++) m = fminf(m, d[j]);
#pragma unroll
      for (int off = 16; off; off >>= 1)
        m = fminf(m, __shfl_xor_sync(0xffffffffu, m, off));
      int li = 0x7fffffff;
#pragma unroll
      for (int j = 0; j < 32; j++)
        if (d[j] == m) li = min(li, lane + j * 32);
#pragma unroll
      for (int off = 16; off; off >>= 1)
        li = min(li, __shfl_xor_sync(0xffffffffu, li, off));
      bv[round] = m;
      bi3[round] = li;
      if ((li & 31) == lane) {
        const int slot = li >> 5;
#pragma unroll
        for (int j = 0; j < 32; j++)
          if (j == slot) d[j] = 1e30f;
      }
    }

    if (lane == 0) {
      float w0 = 1.0f / (bv[0] + 1e-8f);
      float w1 = 1.0f / (bv[1] + 1e-8f);
      float w2 = 1.0f / (bv[2] + 1e-8f);
      float inv = 1.0f / (w0 + w1 + w2);
      kw[p] = float4{w0 * inv, w1 * inv, w2 * inv, 0.0f};
      ki[p] = int4{b * 1024 + bi3[0], b * 1024 + bi3[1], b * 1024 + bi3[2], 0};
    }
    return;
  }

  // ============================ GEMM blocks ================================
  const int warp_m = wid & 3, warp_n = wid >> 2;
  const float* A;
  const __nv_bfloat16 *Bh, *Bl;
  const float* bias;
  float* C;
  int K, bm, bn, prow;
  if (blockIdx.x < 256) {
    int t = blockIdx.x;
    A = A1; Bh = B1h; Bl = B1l; bias = bias1; C = C1;
    K = 1024; bn = (t & 3) * 128; bm = (t >> 2) * 256; prow = 256 + (t >> 2);
  } else {
    int t = blockIdx.x - 256;
    A = A2; Bh = B2h; Bl = B2l; bias = bias2; C = C2;
    K = 512; bn = (t & 3) * 128; bm = (t >> 2) * 256; prow = t >> 2;
  }
  const int NS = K / 32;

  float acc[4][4][4];
#pragma unroll
  for (int i = 0; i < 4; i++)
#pragma unroll
    for (int j = 0; j < 4; j++)
#pragma unroll
      for (int r = 0; r < 4; r++) acc[i][j][r] = 0.0f;

  // prologue: stages 0,1 into bufs 0,1
  stage_load(A, Bh, Bl, K, bm, bn, 0, sb, tid);
  CP_COMMIT();
  stage_load(A, Bh, Bl, K, bm, bn, 32, sb + G_STAGE, tid);
  CP_COMMIT();

  int b0 = 0, b1 = G_STAGE, b2 = 2 * G_STAGE;  // bufs for s, s+1, s+2 (mod 3)
  for (int s = 0; s < NS; s++) {
    CP_WAIT(1);          // group s complete (group s+1 may be pending)
    __syncthreads();     // data of stage s visible; buf of stage s-1 free
    if (s + 2 < NS)      // issue load s+2 into the freed buffer
      stage_load(A, Bh, Bl, K, bm, bn, (s + 2) * 32, sb + b2, tid);
    CP_COMMIT();         // always commit (empty group at tail keeps counts)
    stage_compute(sb + b0, warp_m, warp_n, lid, acc);
    int t = b0; b0 = b1; b1 = b2; b2 = t;  // rotate
  }
  __syncthreads();  // all compute done before smem reuse below

  // ---- epilogue: +bias, store C, per-CTA column sum/sumsq partials ----
  const int g = lid >> 2, tq = lid & 3;
  float s8[4][2], q8[4][2];
#pragma unroll
  for (int j = 0; j < 4; j++) {
    const int n = bn + warp_n * 32 + j * 8 + tq * 2;
    const float2 bv = *reinterpret_cast<const float2*>(bias + n);
    float sv[2] = {0.0f, 0.0f}, qv[2] = {0.0f, 0.0f};
#pragma unroll
    for (int i = 0; i < 4; i++) {
      const int m = bm + warp_m * 64 + i * 16 + g;
      acc[i][j][0] += bv.x;
      acc[i][j][1] += bv.y;
      acc[i][j][2] += bv.x;
      acc[i][j][3] += bv.y;
      float2 r0 = {acc[i][j][0], acc[i][j][1]};
      float2 r1 = {acc[i][j][2], acc[i][j][3]};
      *reinterpret_cast<float2*>(C + (size_t)m * 512 + n) = r0;
      *reinterpret_cast<float2*>(C + (size_t)(m + 8) * 512 + n) = r1;
#pragma unroll
      for (int p = 0; p < 2; p++) {
        sv[p] += acc[i][j][p] + acc[i][j][p + 2];
        qv[p] += acc[i][j][p] * acc[i][j][p] +
                 acc[i][j][p + 2] * acc[i][j][p + 2];
      }
    }
#pragma unroll
    for (int p = 0; p < 2; p++) {
      float svv = sv[p], qvv = qv[p];
      svv += __shfl_down_sync(0xffffffffu, svv, 16);
      qvv += __shfl_down_sync(0xffffffffu, qvv, 16);
      svv += __shfl_down_sync(0xffffffffu, svv, 8);
      qvv += __shfl_down_sync(0xffffffffu, qvv, 8);
      svv += __shfl_down_sync(0xffffffffu, svv, 4);
      qvv += __shfl_down_sync(0xffffffffu, qvv, 4);
      s8[j][p] = svv;
      q8[j][p] = qvv;
    }
  }
  __syncthreads();
  float* red = reinterpret_cast<float*>(smem);
  if (lid < 4) {
#pragma unroll
    for (int j = 0; j < 4; j++)
#pragma unroll
      for (int p = 0; p < 2; p++) {
        int c = warp_n * 32 + j * 8 + lid * 2 + p;  // lid == tq here
        red[warp_m * 128 + c] = s8[j][p];
        red[512 + warp_m * 128 + c] = q8[j][p];
      }
  }
  __syncthreads();
  if (tid < 128) {
    float s = red[tid] + red[128 + tid] + red[256 + tid] + red[384 + tid];
    float q = red[512 + tid] + red[640 + tid] + red[768 + tid] + red[896 + tid];
    part[(size_t)prow * 512 + bn + tid] = s;
    part[262144 + (size_t)prow * 512 + bn + tid] = q;
  }
}

// ---------------------------------------------------------------------------
// BN stats finalize: ONE launch, one block per (path, channel). grid=1024:
// blocks 0..511 -> path2 (rows 0..255), 512..1023 -> path1 (rows 256..319).
// ---------------------------------------------------------------------------
__global__ void __launch_bounds__(256) stats_finalize_all(
    const float* __restrict__ part, const float* __restrict__ bn1_g,
    const float* __restrict__ bn1_b, const float* __restrict__ bn2_g,
    const float* __restrict__ bn2_b, float* __restrict__ ss) {
  __shared__ float rs[256], rq[256];
  const int t = threadIdx.x;
  const bool path1 = blockIdx.x >= 512;
  const int c = blockIdx.x & 511;
  const int row0 = path1 ? 256 : 0;
  const int NBLK = path1 ? 64 : 256;
  const float invM = path1 ? (1.0f / 16384.0f) : (1.0f / 65536.0f);

  float s = 0.0f, q = 0.0f;
  if (t < NBLK) {
    s = part[(size_t)(row0 + t) * 512 + c];
    q = part[262144 + (size_t)(row0 + t) * 512 + c];
  }
  rs[t] = s;
  rq[t] = q;
  __syncthreads();
#pragma unroll
  for (int off = 128; off > 0; off >>= 1) {
    if (t < off) {
      rs[t] += rs[t + off];
      rq[t] += rq[t + off];
    }
    __syncthreads();
  }
  if (t == 0) {
    float mu = rs[0] * invM;
    float var = rq[0] * invM - mu * mu;
    const float* gamma = path1 ? bn1_g : bn2_g;
    const float* beta = path1 ? bn1_b : bn2_b;
    float* dst = path1 ? ss : (ss + 1024);
    float sc = gamma[c] * rsqrtf(var + 1e-5f);
    dst[c] = sc;
    dst[512 + c] = beta[c] - mu * sc;
  }
}

// ---------------------------------------------------------------------------
// Apply: gather 3 feats1 rows + feats2 row, fused BN+ReLU, weighted add.
// ---------------------------------------------------------------------------
__global__ void __launch_bounds__(256) apply_add(
    const float* __restrict__ feats1, const float* __restrict__ feats2,
    const float4* __restrict__ kw, const int4* __restrict__ ki,
    const float* __restrict__ ss1, const float* __restrict__ ss2,
    float* __restrict__ outF) {
  const int lane = threadIdx.x & 31;
  const int row = blockIdx.x * 8 + (threadIdx.x >> 5);

  const float4 wv = kw[row];
  const int4 id = ki[row];
  const float w0 = wv.x, w1 = wv.y, w2 = wv.z;

  const float4* f0 = reinterpret_cast<const float4*>(feats1 + (size_t)id.x * 512);
  const float4* f1 = reinterpret_cast<const float4*>(feats1 + (size_t)id.y * 512);
  const float4* f2 = reinterpret_cast<const float4*>(feats1 + (size_t)id.z * 512);
  const float4* g = reinterpret_cast<const float4*>(feats2 + (size_t)row * 512);
  float4* o = reinterpret_cast<float4*>(outF + (size_t)row * 512);
  const float4* SC1 = reinterpret_cast<const float4*>(ss1);
  const float4* SH1 = reinterpret_cast<const float4*>(ss1 + 512);
  const float4* SC2 = reinterpret_cast<const float4*>(ss2);
  const float4* SH2 = reinterpret_cast<const float4*>(ss2 + 512);

#pragma unroll
  for (int c4 = lane; c4 < 128; c4 += 32) {
    float4 a0 = f0[c4], a1 = f1[c4], a2 = f2[c4], gg = g[c4];
    float4 sc1 = SC1[c4], sh1 = SH1[c4], sc2 = SC2[c4], sh2 = SH2[c4];
    a0.x = fmaxf(fmaf(a0.x, sc1.x, sh1.x), 0.0f);
    a0.y = fmaxf(fmaf(a0.y, sc1.y, sh1.y), 0.0f);
    a0.z = fmaxf(fmaf(a0.z, sc1.z, sh1.z), 0.0f);
    a0.w = fmaxf(fmaf(a0.w, sc1.w, sh1.w), 0.0f);
    a1.x = fmaxf(fmaf(a1.x, sc1.x, sh1.x), 0.0f);
    a1.y = fmaxf(fmaf(a1.y, sc1.y, sh1.y), 0.0f);
    a1.z = fmaxf(fmaf(a1.z, sc1.z, sh1.z), 0.0f);
    a1.w = fmaxf(fmaf(a1.w, sc1.w, sh1.w), 0.0f);
    a2.x = fmaxf(fmaf(a2.x, sc1.x, sh1.x), 0.0f);
    a2.y = fmaxf(fmaf(a2.y, sc1.y, sh1.y), 0.0f);
    a2.z = fmaxf(fmaf(a2.z, sc1.z, sh1.z), 0.0f);
    a2.w = fmaxf(fmaf(a2.w, sc1.w, sh1.w), 0.0f);
    gg.x = fmaxf(fmaf(gg.x, sc2.x, sh2.x), 0.0f);
    gg.y = fmaxf(fmaf(gg.y, sc2.y, sh2.y), 0.0f);
    gg.z = fmaxf(fmaf(gg.z, sc2.z, sh2.z), 0.0f);
    gg.w = fmaxf(fmaf(gg.w, sc2.w, sh2.w), 0.0f);
    float4 r;
    r.x = w0 * a0.x + w1 * a1.x + w2 * a2.x + gg.x;
    r.y = w0 * a0.y + w1 * a1.y + w2 * a2.y + gg.y;
    r.z = w0 * a0.z + w1 * a1.z + w2 * a2.z + gg.z;
    r.w = w0 * a0.w + w1 * a1.w + w2 * a2.w + gg.w;
    o[c4] = r;
  }
}

// ---------------------------------------------------------------------------
extern "C" void kernel_launch(void* const* d_in, const int* in_sizes, int n_in,
                              void* d_out, int out_size) {
  const float* xyz1 = (const float*)d_in[0];
  const float* points1 = (const float*)d_in[1];
  const float* xyz2 = (const float*)d_in[2];
  const float* points2 = (const float*)d_in[3];
  const float* fc1_w = (const float*)d_in[4];
  const float* fc1_b = (const float*)d_in[5];
  const float* bn1_g = (const float*)d_in[6];
  const float* bn1_b = (const float*)d_in[7];
  const float* fc2_w = (const float*)d_in[8];
  const float* fc2_b = (const float*)d_in[9];
  const float* bn2_g = (const float*)d_in[10];
  const float* bn2_b = (const float*)d_in[11];
  float* out = (float*)d_out;

  float *h1, *h2, *part, *ss;
  float4* kw;
  int4* ki;
  __nv_bfloat16 *w1h, *w1l, *w2h, *w2l;
  cudaGetSymbolAddress((void**)&h1, g_h1);
  cudaGetSymbolAddress((void**)&h2, g_h2);
  cudaGetSymbolAddress((void**)&part, g_part);
  cudaGetSymbolAddress((void**)&ss, g_ss);
  cudaGetSymbolAddress((void**)&kw, g_kw);
  cudaGetSymbolAddress((void**)&ki, g_ki);
  cudaGetSymbolAddress((void**)&w1h, g_w1h);
  cudaGetSymbolAddress((void**)&w1l, g_w1l);
  cudaGetSymbolAddress((void**)&w2h, g_w2h);
  cudaGetSymbolAddress((void**)&w2l, g_w2l);

  cudaFuncSetAttribute(gemm_knn_all,
                       cudaFuncAttributeMaxDynamicSharedMemorySize, GEMM_SMEM);

  const size_t featElems = (size_t)16 * 4096 * 512;
  const size_t totalOut = (size_t)out_size;
  const size_t xyzElems = totalOut > featElems ? totalOut - featElems : 0;

  // launch 1: weight transpose + split
  wsplit_all<<<dim3(48, 16), 256>>>(fc1_w, w1h, w1l, fc2_w, w2h, w2l);

  // launch 2: GEMMs (blocks 0..1279) + knn tail backfill (blocks 1280..5375)
  gemm_knn_all<<<5376, 512, GEMM_SMEM>>>(points1, w1h, w1l, fc1_b, h1,
                                         points2, w2h, w2l, fc2_b, h2, part,
                                         xyz2, xyz1, kw, ki);

  // launch 3: BN stats for both paths
  stats_finalize_all<<<1024, 256>>>(part, bn1_g, bn1_b, bn2_g, bn2_b, ss);

  // Output: [xyz2 passthrough | apply(bnrelu(h1) gather) + bnrelu(h2)]
  if (xyzElems > 0) {
    cudaMemcpyAsync(out, xyz2, xyzElems * sizeof(float),
                    cudaMemcpyDeviceToDevice);
  }
  // launch 4: streaming gather+BN+add (high occupancy)
  apply_add<<<8192, 256>>>(h1, h2, kw, ki, ss, ss + 1024, out + xyzElems);
}

// round 17
// speedup vs baseline: 1.0459x; 1.0137x over previous
#include <cuda_runtime.h>
#include <cuda_bf16.h>
#include <cstdint>

// Problem constants: B=16, N1=1024, N2=4096, DIM=512
// GEMM1: M=16384, K=1024, N=512.  GEMM2: M=65536, K=512, N=512.

// ---------------- scratch (no allocations allowed) -------------------------
__device__ float g_h1[16384 * 512];
__device__ float g_h2[65536 * 512];
__device__ float g_part[2 * 512 * 512];    // sums | sumsq (rows 0-255 g2, 256-319 g1)
__device__ float g_ss[4 * 512];            // scale1, shift1, scale2, shift2
__device__ float4 g_kw[65536];             // 3-NN weights per dst point
__device__ int4 g_ki[65536];               // 3-NN global feats1 row ids
__device__ __nv_bfloat16 g_w1h[512 * 1024];
__device__ __nv_bfloat16 g_w1l[512 * 1024];
__device__ __nv_bfloat16 g_w2h[512 * 512];
__device__ __nv_bfloat16 g_w2l[512 * 512];

// ---------------- low-level helpers ----------------------------------------
__device__ __forceinline__ uint32_t smem_to_u32(const void* p) {
  uint32_t a;
  asm("{ .reg .u64 t; cvta.to.shared.u64 t, %1; cvt.u32.u64 %0, t; }"
      : "=r"(a) : "l"(p));
  return a;
}
__device__ __forceinline__ void cp_async16(uint32_t dst, const void* src) {
  asm volatile("cp.async.cg.shared.global [%0], [%1], 16;" ::"r"(dst),
               "l"(src));
}
#define CP_COMMIT() asm volatile("cp.async.commit_group;" ::: "memory")
#define CP_WAIT(N) asm volatile("cp.async.wait_group %0;" ::"n"(N) : "memory")

__device__ __forceinline__ void ldsm_x4(uint32_t (&r)[4], uint32_t addr) {
  asm volatile(
      "ldmatrix.sync.aligned.m8n8.x4.shared.b16 {%0,%1,%2,%3}, [%4];"
      : "=r"(r[0]), "=r"(r[1]), "=r"(r[2]), "=r"(r[3])
      : "r"(addr));
}
__device__ __forceinline__ void lds64(float& f0, float& f1, uint32_t addr) {
  asm volatile("ld.shared.v2.f32 {%0,%1}, [%2];"
               : "=f"(f0), "=f"(f1) : "r"(addr));
}
// fp32 pair -> hi bf16x2 (truncation) + lo bf16x2 (residual, RN)
__device__ __forceinline__ void split_pair(float f0, float f1, uint32_t& h,
                                           uint32_t& l) {
  uint32_t u0 = __float_as_uint(f0), u1 = __float_as_uint(f1);
  h = __byte_perm(u0, u1, 0x7632);  // [u1.hi16 | u0.hi16]
  float r0 = f0 - __uint_as_float(u0 & 0xffff0000u);
  float r1 = f1 - __uint_as_float(u1 & 0xffff0000u);
  asm("cvt.rn.bf16x2.f32 %0, %1, %2;" : "=r"(l) : "f"(r1), "f"(r0));
}
__device__ __forceinline__ void mma_bf16(float (&c)[4], const uint32_t (&a)[4],
                                         uint32_t b0, uint32_t b1) {
  asm("mma.sync.aligned.m16n8k16.row.col.f32.bf16.bf16.f32 "
      "{%0,%1,%2,%3}, {%4,%5,%6,%7}, {%8,%9}, {%0,%1,%2,%3};"
      : "+f"(c[0]), "+f"(c[1]), "+f"(c[2]), "+f"(c[3])
      : "r"(a[0]), "r"(a[1]), "r"(a[2]), "r"(a[3]), "r"(b0), "r"(b1));
}

// ---------------------------------------------------------------------------
// Both weights in one launch: W [K,512] -> Wt hi/lo [512,K] transpose + split.
// ---------------------------------------------------------------------------
__global__ void __launch_bounds__(256) wsplit_all(
    const float* __restrict__ W1, __nv_bfloat16* __restrict__ T1h,
    __nv_bfloat16* __restrict__ T1l, const float* __restrict__ W2,
    __nv_bfloat16* __restrict__ T2h, __nv_bfloat16* __restrict__ T2l) {
  __shared__ float tl[32][33];
  const bool first = blockIdx.x < 32;
  const int K = first ? 1024 : 512;
  const float* W = first ? W1 : W2;
  __nv_bfloat16* Th = first ? T1h : T2h;
  __nv_bfloat16* Tl = first ? T1l : T2l;
  int k0 = (first ? blockIdx.x : (blockIdx.x - 32)) * 32;
  int n0 = blockIdx.y * 32;
  int x = threadIdx.x & 31, y = threadIdx.x >> 5;  // 32x8
  for (int i = y; i < 32; i += 8)
    tl[i][x] = W[(size_t)(k0 + i) * 512 + n0 + x];
  __syncthreads();
  for (int i = y; i < 32; i += 8) {
    float v = tl[x][i];  // = W[k0+x][n0+i]
    __nv_bfloat16 h = __float2bfloat16(v);
    __nv_bfloat16 l = __float2bfloat16(v - __bfloat162float(h));
    Th[(size_t)(n0 + i) * K + k0 + x] = h;
    Tl[(size_t)(n0 + i) * K + k0 + x] = l;
  }
}

// ---------------------------------------------------------------------------
// FUSED launch: blocks 0..255 -> fc1 GEMM (K=1024); 256..1279 -> fc2 GEMM
// (K=512); 1280..5375 -> 3-NN knn blocks (16 points each) that BACKFILL the
// GEMM's ragged tail waves. bf16x3 GEMM via mma.sync: CTA tile 256x128,
// Kc=32, three-buffer single-barrier pipeline, 512 thr, warp grid 4m x 4n.
// Epilogue emits per-CTA BN partials.
// ---------------------------------------------------------------------------
static constexpr int A_RS = 160;                  // 32 fp32 + 32B pad (bank-clean)
static constexpr int A_BYTES = 256 * A_RS;        // 40960 B
static constexpr int B_RS = 80;                   // 32 bf16 + 16B pad
static constexpr int B_TILE = 128 * B_RS;         // 10240 B
static constexpr int G_STAGE = A_BYTES + 2 * B_TILE;  // 61440 B
static constexpr int GEMM_SMEM = 3 * G_STAGE;     // 184320 B

__device__ __forceinline__ void stage_load(
    const float* __restrict__ A, const __nv_bfloat16* __restrict__ Bh,
    const __nv_bfloat16* __restrict__ Bl, int K, int bm, int bn, int k0,
    uint32_t base, int tid) {
  // A fp32 tile: 256 rows x 8 ld16 (128B) = 2048 -> 4 per thread
  {
    const float* sa = A + (size_t)bm * K;
#pragma unroll
    for (int i = 0; i < 4; i++) {
      int q = tid + i * 512;  // 0..2047
      int row = q >> 3, seg = q & 7;
      cp_async16(base + row * A_RS + seg * 16,
                 sa + (size_t)row * K + k0 + seg * 4);
    }
  }
  // B hi/lo bf16 tiles: 128 rows x 4 ld16 (64B) = 512 each -> 1 per thread
  {
    const __nv_bfloat16* sbh = Bh + (size_t)bn * K;
    const __nv_bfloat16* sbl = Bl + (size_t)bn * K;
    int row = tid >> 2, seg = tid & 3;
    size_t go = (size_t)row * K + k0 + seg * 8;
    uint32_t so = row * B_RS + seg * 16;
    cp_async16(base + A_BYTES + so, sbh + go);
    cp_async16(base + A_BYTES + B_TILE + so, sbl + go);
  }
}

__device__ __forceinline__ void stage_compute(uint32_t base, int warp_m,
                                              int warp_n, int lid,
                                              float acc[4][4][4]) {
  const uint32_t aF = base + (warp_m * 64 + (lid >> 2)) * A_RS + (lid & 3) * 8;
  const int nrow = warp_n * 32 + (lid & 7) + ((lid >> 4) & 1) * 8;
  const uint32_t b_base =
      base + A_BYTES + nrow * B_RS + ((lid >> 3) & 1) * 16;
#pragma unroll
  for (int kk = 0; kk < 2; kk++) {
    uint32_t ah[4][4], al[4][4], bh[2][4], bl[2][4];
    const uint32_t akk = aF + kk * 64;
#pragma unroll
    for (int i = 0; i < 4; i++) {
      const uint32_t ai = akk + i * (16 * A_RS);
#pragma unroll
      for (int r = 0; r < 4; r++) {
        float f0, f1;
        lds64(f0, f1, ai + (r & 1) * (8 * A_RS) + (r >> 1) * 32);
        split_pair(f0, f1, ah[i][r], al[i][r]);
      }
    }
    const int kb = kk * 32;
#pragma unroll
    for (int jj = 0; jj < 2; jj++) {
      ldsm_x4(bh[jj], b_base + jj * (16 * B_RS) + kb);
      ldsm_x4(bl[jj], b_base + B_TILE + jj * (16 * B_RS) + kb);
    }
#pragma unroll
    for (int i = 0; i < 4; i++)
#pragma unroll
      for (int j = 0; j < 4; j++) {
        const int jj = j >> 1, o = (j & 1) * 2;
        mma_bf16(acc[i][j], ah[i], bh[jj][o], bh[jj][o + 1]);
      }
#pragma unroll
    for (int i = 0; i < 4; i++)
#pragma unroll
      for (int j = 0; j < 4; j++) {
        const int jj = j >> 1, o = (j & 1) * 2;
        mma_bf16(acc[i][j], ah[i], bl[jj][o], bl[jj][o + 1]);
      }
#pragma unroll
    for (int i = 0; i < 4; i++)
#pragma unroll
      for (int j = 0; j < 4; j++) {
        const int jj = j >> 1, o = (j & 1) * 2;
        mma_bf16(acc[i][j], al[i], bh[jj][o], bh[jj][o + 1]);
      }
  }
}

__global__ void __launch_bounds__(512, 1) gemm_knn_all(
    const float* __restrict__ A1, const __nv_bfloat16* __restrict__ B1h,
    const __nv_bfloat16* __restrict__ B1l, const float* __restrict__ bias1,
    float* __restrict__ C1, const float* __restrict__ A2,
    const __nv_bfloat16* __restrict__ B2h,
    const __nv_bfloat16* __restrict__ B2l, const float* __restrict__ bias2,
    float* __restrict__ C2, float* __restrict__ part,
    const float* __restrict__ xyz2, const float* __restrict__ xyz1,
    float4* __restrict__ kw, int4* __restrict__ ki) {
  extern __shared__ char smem[];
  const uint32_t sb = smem_to_u32(smem);
  const int tid = threadIdx.x;
  const int wid = tid >> 5, lid = tid & 31;

  // ======================= knn blocks (tail backfill) ======================
  if (blockIdx.x >= 1280) {
    float* sx = reinterpret_cast<float*>(smem);
    float* sy = sx + 1024;
    float* sz = sy + 1024;
    const int kb = blockIdx.x - 1280;     // 0..4095
    const int b = kb >> 8;                // 256 blocks per batch
    const int nb = (kb & 255) * 16;       // 16 points per block
    const int w = wid, lane = lid;

    const float* src = xyz1 + (size_t)b * 3072;
    for (int i = tid; i < 1024; i += 512) {
      sx[i] = src[3 * i + 0];
      sy[i] = src[3 * i + 1];
      sz[i] = src[3 * i + 2];
    }
    __syncthreads();

    const int n = nb + w;
    const int p = b * 4096 + n;
    const float* pd = xyz2 + (size_t)p * 3;
    const float px = pd[0], py = pd[1], pz = pd[2];
    const float pp = px * px + py * py + pz * pz;

    float d[32];
#pragma unroll
    for (int j = 0; j < 32; j++) {
      int s = lane + j * 32;
      float xx = sx[s], yy = sy[s], zz = sz[s];
      d[j] = pp + (xx * xx + yy * yy + zz * zz) -
             2.0f * (px * xx + py * yy + pz * zz);
    }

    float bv[3];
    int bi3[3];
#pragma unroll
    for (int round = 0; round < 3; round++) {
      float m = d[0];
#pragma unroll
      for (int j = 1; j < 32; j++) m = fminf(m, d[j]);
#pragma unroll
      for (int off = 16; off; off >>= 1)
        m = fminf(m, __shfl_xor_sync(0xffffffffu, m, off));
      int li = 0x7fffffff;
#pragma unroll
      for (int j = 0; j < 32; j++)
        if (d[j] == m) li = min(li, lane + j * 32);
#pragma unroll
      for (int off = 16; off; off >>= 1)
        li = min(li, __shfl_xor_sync(0xffffffffu, li, off));
      bv[round] = m;
      bi3[round] = li;
      if ((li & 31) == lane) {
        const int slot = li >> 5;
#pragma unroll
        for (int j = 0; j < 32; j++)
          if (j == slot) d[j] = 1e30f;
      }
    }

    if (lane == 0) {
      float w0 = 1.0f / (bv[0] + 1e-8f);
      float w1 = 1.0f / (bv[1] + 1e-8f);
      float w2 = 1.0f / (bv[2] + 1e-8f);
      float inv = 1.0f / (w0 + w1 + w2);
      kw[p] = float4{w0 * inv, w1 * inv, w2 * inv, 0.0f};
      ki[p] = int4{b * 1024 + bi3[0], b * 1024 + bi3[1], b * 1024 + bi3[2], 0};
    }
    return;
  }

  // ============================ GEMM blocks ================================
  const int warp_m = wid & 3, warp_n = wid >> 2;
  const float* A;
  const __nv_bfloat16 *Bh, *Bl;
  const float* bias;
  float* C;
  int K, bm, bn, prow;
  if (blockIdx.x < 256) {
    int t = blockIdx.x;
    A = A1; Bh = B1h; Bl = B1l; bias = bias1; C = C1;
    K = 1024; bn = (t & 3) * 128; bm = (t >> 2) * 256; prow = 256 + (t >> 2);
  } else {
    int t = blockIdx.x - 256;
    A = A2; Bh = B2h; Bl = B2l; bias = bias2; C = C2;
    K = 512; bn = (t & 3) * 128; bm = (t >> 2) * 256; prow = t >> 2;
  }
  const int NS = K / 32;

  float acc[4][4][4];
#pragma unroll
  for (int i = 0; i < 4; i++)
#pragma unroll
    for (int j = 0; j < 4; j++)
#pragma unroll
      for (int r = 0; r < 4; r++) acc[i][j][r] = 0.0f;

  // prologue: stages 0,1 into bufs 0,1
  stage_load(A, Bh, Bl, K, bm, bn, 0, sb, tid);
  CP_COMMIT();
  stage_load(A, Bh, Bl, K, bm, bn, 32, sb + G_STAGE, tid);
  CP_COMMIT();

  int b0 = 0, b1 = G_STAGE, b2 = 2 * G_STAGE;  // bufs for s, s+1, s+2 (mod 3)
  for (int s = 0; s < NS; s++) {
    CP_WAIT(1);          // group s complete (group s+1 may be pending)
    __syncthreads();     // data of stage s visible; buf of stage s-1 free
    if (s + 2 < NS)      // issue load s+2 into the freed buffer
      stage_load(A, Bh, Bl, K, bm, bn, (s + 2) * 32, sb + b2, tid);
    CP_COMMIT();         // always commit (empty group at tail keeps counts)
    stage_compute(sb + b0, warp_m, warp_n, lid, acc);
    int t = b0; b0 = b1; b1 = b2; b2 = t;  // rotate
  }
  __syncthreads();  // all compute done before smem reuse below

  // ---- epilogue: +bias, store C, per-CTA column sum/sumsq partials ----
  const int g = lid >> 2, tq = lid & 3;
  float s8[4][2], q8[4][2];
#pragma unroll
  for (int j = 0; j < 4; j++) {
    const int n = bn + warp_n * 32 + j * 8 + tq * 2;
    const float2 bv = *reinterpret_cast<const float2*>(bias + n);
    float sv[2] = {0.0f, 0.0f}, qv[2] = {0.0f, 0.0f};
#pragma unroll
    for (int i = 0; i < 4; i++) {
      const int m = bm + warp_m * 64 + i * 16 + g;
      acc[i][j][0] += bv.x;
      acc[i][j][1] += bv.y;
      acc[i][j][2] += bv.x;
      acc[i][j][3] += bv.y;
      float2 r0 = {acc[i][j][0], acc[i][j][1]};
      float2 r1 = {acc[i][j][2], acc[i][j][3]};
      *reinterpret_cast<float2*>(C + (size_t)m * 512 + n) = r0;
      *reinterpret_cast<float2*>(C + (size_t)(m + 8) * 512 + n) = r1;
#pragma unroll
      for (int p = 0; p < 2; p++) {
        sv[p] += acc[i][j][p] + acc[i][j][p + 2];
        qv[p] += acc[i][j][p] * acc[i][j][p] +
                 acc[i][j][p + 2] * acc[i][j][p + 2];
      }
    }
#pragma unroll
    for (int p = 0; p < 2; p++) {
      float svv = sv[p], qvv = qv[p];
      svv += __shfl_down_sync(0xffffffffu, svv, 16);
      qvv += __shfl_down_sync(0xffffffffu, qvv, 16);
      svv += __shfl_down_sync(0xffffffffu, svv, 8);
      qvv += __shfl_down_sync(0xffffffffu, qvv, 8);
      svv += __shfl_down_sync(0xffffffffu, svv, 4);
      qvv += __shfl_down_sync(0xffffffffu, qvv, 4);
      s8[j][p] = svv;
      q8[j][p] = qvv;
    }
  }
  __syncthreads();
  float* red = reinterpret_cast<float*>(smem);
  if (lid < 4) {
#pragma unroll
    for (int j = 0; j < 4; j++)
#pragma unroll
      for (int p = 0; p < 2; p++) {
        int c = warp_n * 32 + j * 8 + lid * 2 + p;  // lid == tq here
        red[warp_m * 128 + c] = s8[j][p];
        red[512 + warp_m * 128 + c] = q8[j][p];
      }
  }
  __syncthreads();
  if (tid < 128) {
    float s = red[tid] + red[128 + tid] + red[256 + tid] + red[384 + tid];
    float q = red[512 + tid] + red[640 + tid] + red[768 + tid] + red[896 + tid];
    part[(size_t)prow * 512 + bn + tid] = s;
    part[262144 + (size_t)prow * 512 + bn + tid] = q;
  }
}

// ---------------------------------------------------------------------------
// BN stats finalize: ONE launch, one block per (path, channel). grid=1024:
// blocks 0..511 -> path2 (rows 0..255), 512..1023 -> path1 (rows 256..319).
// ---------------------------------------------------------------------------
__global__ void __launch_bounds__(256) stats_finalize_all(
    const float* __restrict__ part, const float* __restrict__ bn1_g,
    const float* __restrict__ bn1_b, const float* __restrict__ bn2_g,
    const float* __restrict__ bn2_b, float* __restrict__ ss) {
  __shared__ float rs[256], rq[256];
  const int t = threadIdx.x;
  const bool path1 = blockIdx.x >= 512;
  const int c = blockIdx.x & 511;
  const int row0 = path1 ? 256 : 0;
  const int NBLK = path1 ? 64 : 256;
  const float invM = path1 ? (1.0f / 16384.0f) : (1.0f / 65536.0f);

  float s = 0.0f, q = 0.0f;
  if (t < NBLK) {
    s = part[(size_t)(row0 + t) * 512 + c];
    q = part[262144 + (size_t)(row0 + t) * 512 + c];
  }
  rs[t] = s;
  rq[t] = q;
  __syncthreads();
#pragma unroll
  for (int off = 128; off > 0; off >>= 1) {
    if (t < off) {
      rs[t] += rs[t + off];
      rq[t] += rq[t + off];
    }
    __syncthreads();
  }
  if (t == 0) {
    float mu = rs[0] * invM;
    float var = rq[0] * invM - mu * mu;
    const float* gamma = path1 ? bn1_g : bn2_g;
    const float* beta = path1 ? bn1_b : bn2_b;
    float* dst = path1 ? ss : (ss + 1024);
    float sc = gamma[c] * rsqrtf(var + 1e-5f);
    dst[c] = sc;
    dst[512 + c] = beta[c] - mu * sc;
  }
}

// ---------------------------------------------------------------------------
// Apply: gather 3 feats1 rows + feats2 row, fused BN+ReLU, weighted add.
// Scale/shift tables staged in SMEM once per block (kills redundant L1
// traffic). Blocks >= 8192 copy the xyz2 passthrough (replaces memcpyAsync).
// ---------------------------------------------------------------------------
__global__ void __launch_bounds__(256) apply_add(
    const float* __restrict__ feats1, const float* __restrict__ feats2,
    const float4* __restrict__ kw, const int4* __restrict__ ki,
    const float* __restrict__ ss1, const float* __restrict__ ss2,
    float* __restrict__ outF, const float* __restrict__ xyz2,
    float* __restrict__ outX, int nCopy4) {
  // xyz2 passthrough blocks
  if (blockIdx.x >= 8192) {
    int i = (blockIdx.x - 8192) * 256 + threadIdx.x;
    if (i < nCopy4)
      reinterpret_cast<float4*>(outX)[i] =
          reinterpret_cast<const float4*>(xyz2)[i];
    return;
  }

  __shared__ float4 s_sc1[128], s_sh1[128], s_sc2[128], s_sh2[128];  // 8 KB
  const int tid = threadIdx.x;
  for (int i = tid; i < 128; i += 256) {
    s_sc1[i] = reinterpret_cast<const float4*>(ss1)[i];
    s_sh1[i] = reinterpret_cast<const float4*>(ss1 + 512)[i];
    s_sc2[i] = reinterpret_cast<const float4*>(ss2)[i];
    s_sh2[i] = reinterpret_cast<const float4*>(ss2 + 512)[i];
  }
  __syncthreads();

  const int lane = tid & 31;
  const int row = blockIdx.x * 8 + (tid >> 5);

  const float4 wv = kw[row];
  const int4 id = ki[row];
  const float w0 = wv.x, w1 = wv.y, w2 = wv.z;

  const float4* f0 = reinterpret_cast<const float4*>(feats1 + (size_t)id.x * 512);
  const float4* f1 = reinterpret_cast<const float4*>(feats1 + (size_t)id.y * 512);
  const float4* f2 = reinterpret_cast<const float4*>(feats1 + (size_t)id.z * 512);
  const float4* g = reinterpret_cast<const float4*>(feats2 + (size_t)row * 512);
  float4* o = reinterpret_cast<float4*>(outF + (size_t)row * 512);

#pragma unroll
  for (int c4 = lane; c4 < 128; c4 += 32) {
    float4 a0 = f0[c4], a1 = f1[c4], a2 = f2[c4], gg = g[c4];
    float4 sc1 = s_sc1[c4], sh1 = s_sh1[c4], sc2 = s_sc2[c4], sh2 = s_sh2[c4];
    a0.x = fmaxf(fmaf(a0.x, sc1.x, sh1.x), 0.0f);
    a0.y = fmaxf(fmaf(a0.y, sc1.y, sh1.y), 0.0f);
    a0.z = fmaxf(fmaf(a0.z, sc1.z, sh1.z), 0.0f);
    a0.w = fmaxf(fmaf(a0.w, sc1.w, sh1.w), 0.0f);
    a1.x = fmaxf(fmaf(a1.x, sc1.x, sh1.x), 0.0f);
    a1.y = fmaxf(fmaf(a1.y, sc1.y, sh1.y), 0.0f);
    a1.z = fmaxf(fmaf(a1.z, sc1.z, sh1.z), 0.0f);
    a1.w = fmaxf(fmaf(a1.w, sc1.w, sh1.w), 0.0f);
    a2.x = fmaxf(fmaf(a2.x, sc1.x, sh1.x), 0.0f);
    a2.y = fmaxf(fmaf(a2.y, sc1.y, sh1.y), 0.0f);
    a2.z = fmaxf(fmaf(a2.z, sc1.z, sh1.z), 0.0f);
    a2.w = fmaxf(fmaf(a2.w, sc1.w, sh1.w), 0.0f);
    gg.x = fmaxf(fmaf(gg.x, sc2.x, sh2.x), 0.0f);
    gg.y = fmaxf(fmaf(gg.y, sc2.y, sh2.y), 0.0f);
    gg.z = fmaxf(fmaf(gg.z, sc2.z, sh2.z), 0.0f);
    gg.w = fmaxf(fmaf(gg.w, sc2.w, sh2.w), 0.0f);
    float4 r;
    r.x = w0 * a0.x + w1 * a1.x + w2 * a2.x + gg.x;
    r.y = w0 * a0.y + w1 * a1.y + w2 * a2.y + gg.y;
    r.z = w0 * a0.z + w1 * a1.z + w2 * a2.z + gg.z;
    r.w = w0 * a0.w + w1 * a1.w + w2 * a2.w + gg.w;
    o[c4] = r;
  }
}

// ---------------------------------------------------------------------------
extern "C" void kernel_launch(void* const* d_in, const int* in_sizes, int n_in,
                              void* d_out, int out_size) {
  const float* xyz1 = (const float*)d_in[0];
  const float* points1 = (const float*)d_in[1];
  const float* xyz2 = (const float*)d_in[2];
  const float* points2 = (const float*)d_in[3];
  const float* fc1_w = (const float*)d_in[4];
  const float* fc1_b = (const float*)d_in[5];
  const float* bn1_g = (const float*)d_in[6];
  const float* bn1_b = (const float*)d_in[7];
  const float* fc2_w = (const float*)d_in[8];
  const float* fc2_b = (const float*)d_in[9];
  const float* bn2_g = (const float*)d_in[10];
  const float* bn2_b = (const float*)d_in[11];
  float* out = (float*)d_out;

  float *h1, *h2, *part, *ss;
  float4* kw;
  int4* ki;
  __nv_bfloat16 *w1h, *w1l, *w2h, *w2l;
  cudaGetSymbolAddress((void**)&h1, g_h1);
  cudaGetSymbolAddress((void**)&h2, g_h2);
  cudaGetSymbolAddress((void**)&part, g_part);
  cudaGetSymbolAddress((void**)&ss, g_ss);
  cudaGetSymbolAddress((void**)&kw, g_kw);
  cudaGetSymbolAddress((void**)&ki, g_ki);
  cudaGetSymbolAddress((void**)&w1h, g_w1h);
  cudaGetSymbolAddress((void**)&w1l, g_w1l);
  cudaGetSymbolAddress((void**)&w2h, g_w2h);
  cudaGetSymbolAddress((void**)&w2l, g_w2l);

  cudaFuncSetAttribute(gemm_knn_all,
                       cudaFuncAttributeMaxDynamicSharedMemorySize, GEMM_SMEM);

  const size_t featElems = (size_t)16 * 4096 * 512;
  const size_t totalOut = (size_t)out_size;
  const size_t xyzElems = totalOut > featElems ? totalOut - featElems : 0;
  const int nCopy4 = (int)(xyzElems / 4);
  const int copyBlocks = (nCopy4 + 255) / 256;

  // launch 1: weight transpose + split
  wsplit_all<<<dim3(48, 16), 256>>>(fc1_w, w1h, w1l, fc2_w, w2h, w2l);

  // launch 2: GEMMs (blocks 0..1279) + knn tail backfill (blocks 1280..5375)
  gemm_knn_all<<<5376, 512, GEMM_SMEM>>>(points1, w1h, w1l, fc1_b, h1,
                                         points2, w2h, w2l, fc2_b, h2, part,
                                         xyz2, xyz1, kw, ki);

  // launch 3: BN stats for both paths
  stats_finalize_all<<<1024, 256>>>(part, bn1_g, bn1_b, bn2_g, bn2_b, ss);

  // launch 4: apply (+ fused xyz2 passthrough copy blocks)
  apply_add<<<8192 + copyBlocks, 256>>>(h1, h2, kw, ki, ss, ss + 1024,
                                        out + xyzElems, xyz2, out, nCopy4);
}